// round 10
// baseline (speedup 1.0000x reference)
#include <cuda_runtime.h>
#include <cstdint>

#define NHEAD 16
#define QLEN  4096
#define KLEN  4096
#define DIM   64
#define BQ    128
#define BK    64
#define NTHREADS 128
#define NITER (KLEN / BK)

#define KSS 72   // K tile row stride (words): LDS.64 banks 8g+2b (CF)
#define VRP 136  // V rowpair stride (words): LDS.64 banks 8b+2g (CF)
#define VGR 544  // V group stride = 4*VRP
#define PSS 72   // P pad row stride: LDS.64 banks 8g+2b (CF); STS.32 8g+pos (CF)

#define STAGE_K_FLOATS (64 * KSS)                     // 4608
#define STAGE_V_FLOATS (8 * VGR)                      // 4352
#define STAGE_FLOATS   (STAGE_K_FLOATS + STAGE_V_FLOATS) // 8960
#define PS_OFF         (2 * STAGE_FLOATS)             // 17920
#define SMEM_FLOATS    (PS_OFF + 4 * 32 * PSS)        // 27136
#define SMEM_BYTES     (SMEM_FLOATS * 4)              // 108544

// pre-permuted, tf32-rounded K/V scratch (static __device__: allocation-free)
// g_Kp[h][n][pos] : pos(k) = (k&~7) + (k&3)*2 + ((k>>2)&1)   (column-pair interleave)
// g_Vp[h]: element (k,n) at (k>>3)*512 + (k&3)*128 + n*2 + ((k>>2)&1)
__device__ uint32_t g_Kp[NHEAD * KLEN * DIM];
__device__ uint32_t g_Vp[NHEAD * KLEN * DIM];

__device__ __forceinline__ uint32_t f2tf(float x) {
    uint32_t r; asm("cvt.rna.tf32.f32 %0, %1;" : "=r"(r) : "f"(x)); return r;
}
__device__ __forceinline__ float fast_exp2(float x) {
    float y; asm("ex2.approx.ftz.f32 %0, %1;" : "=f"(y) : "f"(x)); return y;
}
__device__ __forceinline__ uint32_t smem_u32(const void* p) {
    uint32_t a;
    asm("{ .reg .u64 t; cvta.to.shared.u64 t, %1; cvt.u32.u64 %0, t; }" : "=r"(a) : "l"(p));
    return a;
}
__device__ __forceinline__ void cp16(uint32_t dst, const void* src) {
    asm volatile("cp.async.ca.shared.global [%0], [%1], 16;" :: "r"(dst), "l"(src) : "memory");
}
#define CP_COMMIT() asm volatile("cp.async.commit_group;" ::: "memory")
#define CP_WAIT1()  asm volatile("cp.async.wait_group 1;" ::: "memory")

// D(16x8,f32) += A(16x8,tf32) * B(8x8,tf32)   [row.col]
__device__ __forceinline__ void mma_tf32(float* d, const uint32_t* a,
                                         uint32_t b0, uint32_t b1) {
    asm volatile(
        "mma.sync.aligned.m16n8k8.row.col.f32.tf32.tf32.f32 "
        "{%0,%1,%2,%3}, {%4,%5,%6,%7}, {%8,%9}, {%0,%1,%2,%3};"
        : "+f"(d[0]), "+f"(d[1]), "+f"(d[2]), "+f"(d[3])
        : "r"(a[0]), "r"(a[1]), "r"(a[2]), "r"(a[3]), "r"(b0), "r"(b1));
}

// ---- prepass: tf32-round AND permute K,V (one uint4 of each per thread) ----
extern "C" __global__ void __launch_bounds__(256)
kv_permute(const float* __restrict__ ks, const float* __restrict__ vs)
{
    const size_t i = (size_t)blockIdx.x * 256 + threadIdx.x;  // uint4 index
    const size_t w = i * 4;                                   // word index
    const size_t h = w >> 18;                                 // 262144 words/head
    const int rem = (int)(w & 262143);

    // K: dest row n, positions p0..p0+3; k(p) = (p&~7) + ((p&1)<<2) + ((p>>1)&3)
    {
        const int n = rem >> 6, p0 = rem & 63;
        const float* src = ks + h * 262144 + (size_t)n * 64;
        uint32_t r[4];
        #pragma unroll
        for (int t = 0; t < 4; t++) {
            const int p = p0 + t;
            const int k = (p & ~7) + ((p & 1) << 2) + ((p >> 1) & 3);
            r[t] = f2tf(src[k]);
        }
        ((uint4*)g_Kp)[i] = make_uint4(r[0], r[1], r[2], r[3]);
    }
    // V: dest (grp, rp, words n*2+par); quad = {(k0,n0),(k1,n0),(k0,n1),(k1,n1)}
    {
        const int grp = rem >> 9, rp = (rem >> 7) & 3, w128 = rem & 127;
        const int n0 = w128 >> 1;
        const int kA = grp * 8 + rp, kB = kA + 4;
        const float* src = vs + h * 262144;
        uint4 r;
        r.x = f2tf(src[(size_t)kA * 64 + n0]);
        r.y = f2tf(src[(size_t)kB * 64 + n0]);
        r.z = f2tf(src[(size_t)kA * 64 + n0 + 1]);
        r.w = f2tf(src[(size_t)kB * 64 + n0 + 1]);
        ((uint4*)g_Vp)[i] = r;
    }
}

extern "C" __global__ void __launch_bounds__(NTHREADS, 2)
fa_hmma_v64(const float* __restrict__ qs, const unsigned int* __restrict__ maskw,
            float* __restrict__ out)
{
    extern __shared__ float sm[];
    const uint32_t sb = smem_u32(sm);

    const int tid  = threadIdx.x;
    const int w    = tid >> 5;
    const int lane = tid & 31;
    const int g    = lane >> 2;   // row within 8
    const int b    = lane & 3;    // k/col selector

    uint32_t* PwU = (uint32_t*)(sm + PS_OFF) + w * 32 * PSS;  // warp P pad [32][PSS]
    // P store positions for cols 2b, 2b+1 (column-pair permutation)
    const int pe = ((2 * b) & 3) * 2 + (b >> 1);
    const int po = pe + 2;

    const int head = blockIdx.y;
    const int q0   = blockIdx.x * BQ;
    const int r0   = w * 32 + g;             // q rows r0, +8, +16, +24

    const float qscale = 0.125f * 1.44269504088896340736f;  // 1/sqrt(D)*log2(e)
    const float* qg = qs + ((size_t)head * QLEN + q0) * DIM;
    const uint32_t* kg = g_Kp + (size_t)head * KLEN * DIM;
    const uint32_t* vg = g_Vp + (size_t)head * KLEN * DIM;

    // ---- prologue: prefetch stage 0 (K permuted rows + V permuted groups) ----
    {
        #pragma unroll
        for (int i = 0; i < 8; i++) {
            const int idx = tid + NTHREADS * i;
            const int r = idx >> 4, c4 = (idx & 15) * 4;
            cp16(sb + (r * KSS + c4) * 4, kg + (size_t)r * 64 + c4);
            const int grp = idx >> 7, rp = (idx >> 5) & 3, q4 = idx & 31;
            cp16(sb + (STAGE_K_FLOATS + grp * VGR + rp * VRP + q4 * 4) * 4,
                 vg + grp * 512 + rp * 128 + q4 * 4);
        }
        CP_COMMIT();
    }

    // ---- persistent Q A-fragments (plain gmem layout; loaded once) ----
    uint32_t qa[8][8];
    {
        const float* q0p = qg + (size_t)r0 * DIM;
        const float* q1p = q0p + 8 * DIM;
        const float* q2p = q0p + 16 * DIM;
        const float* q3p = q0p + 24 * DIM;
        #pragma unroll
        for (int c = 0; c < 8; c++) {
            const int k0c = c * 8 + b;
            qa[c][0] = f2tf(q0p[k0c]     * qscale);
            qa[c][1] = f2tf(q1p[k0c]     * qscale);
            qa[c][2] = f2tf(q0p[k0c + 4] * qscale);
            qa[c][3] = f2tf(q1p[k0c + 4] * qscale);
            qa[c][4] = f2tf(q2p[k0c]     * qscale);
            qa[c][5] = f2tf(q3p[k0c]     * qscale);
            qa[c][6] = f2tf(q2p[k0c + 4] * qscale);
            qa[c][7] = f2tf(q3p[k0c + 4] * qscale);
        }
    }

    float o[8][8];
    #pragma unroll
    for (int j = 0; j < 8; j++)
        #pragma unroll
        for (int e = 0; e < 8; e++) o[j][e] = 0.0f;
    float mrun[4] = {-1e30f, -1e30f, -1e30f, -1e30f};
    float lrun[4] = {0.0f, 0.0f, 0.0f, 0.0f};

    for (int it = 0; it < NITER; it++) {
        const int k0 = it * BK;
        const int stage = it & 1;
        const int kb = k0 >> 2;

        // ---- prefetch next tile into other stage ----
        {
            const int knx = (it + 1 < NITER ? it + 1 : it) * BK;
            const uint32_t sbase = sb + ((1 - stage) * STAGE_FLOATS) * 4;
            #pragma unroll
            for (int i = 0; i < 8; i++) {
                const int idx = tid + NTHREADS * i;
                const int r = idx >> 4, c4 = (idx & 15) * 4;
                cp16(sbase + (r * KSS + c4) * 4, kg + (size_t)(knx + r) * 64 + c4);
                const int grp = idx >> 7, rp = (idx >> 5) & 3, q4 = idx & 31;
                cp16(sbase + (STAGE_K_FLOATS + grp * VGR + rp * VRP + q4 * 4) * 4,
                     vg + (size_t)knx * 64 + grp * 512 + rp * 128 + q4 * 4);
            }
            CP_COMMIT();
        }
        CP_WAIT1();          // this stage's data landed
        __syncthreads();     // all threads' data visible; prev-iter reads done

        const uint32_t* KsU = (const uint32_t*)(sm + stage * STAGE_FLOATS);
        const uint32_t* VsU = KsU + STAGE_K_FLOATS;

        // ---- S = Q @ K^T : LDS.64 B fragments, shared by both A row-blocks ----
        float sacc[8][8];
        #pragma unroll
        for (int j = 0; j < 8; j++)
            #pragma unroll
            for (int e = 0; e < 8; e++) sacc[j][e] = 0.0f;

        #pragma unroll
        for (int c = 0; c < 8; c++) {
            #pragma unroll
            for (int j = 0; j < 8; j++) {
                const uint2 kk = *(const uint2*)&KsU[(j * 8 + g) * KSS + c * 8 + 2 * b];
                mma_tf32(&sacc[j][0], &qa[c][0], kk.x, kk.y);
                mma_tf32(&sacc[j][4], &qa[c][4], kk.x, kk.y);
            }
        }

        // ---- mask (robust word-of-4; all-true -> never taken) ----
        #pragma unroll
        for (int j = 0; j < 8; j++) {
            if (maskw[kb + 2 * j + (b >> 1)] == 0u) {
                #pragma unroll
                for (int e = 0; e < 8; e++) sacc[j][e] = -1e30f;
            }
        }

        // ---- online softmax (log2 domain), 4 row-blocks ----
        float m[4] = {-1e30f, -1e30f, -1e30f, -1e30f};
        #pragma unroll
        for (int j = 0; j < 8; j++)
            #pragma unroll
            for (int i = 0; i < 4; i++)
                m[i] = fmaxf(m[i], fmaxf(sacc[j][2 * i], sacc[j][2 * i + 1]));
        #pragma unroll
        for (int i = 0; i < 4; i++) {
            m[i] = fmaxf(m[i], __shfl_xor_sync(0xffffffffu, m[i], 1));
            m[i] = fmaxf(m[i], __shfl_xor_sync(0xffffffffu, m[i], 2));
        }
        float al[4];
        #pragma unroll
        for (int i = 0; i < 4; i++) {
            const float mn = fmaxf(mrun[i], m[i]);
            al[i] = fast_exp2(mrun[i] - mn);
            mrun[i] = mn;
        }
        float l[4] = {0.0f, 0.0f, 0.0f, 0.0f};
        #pragma unroll
        for (int j = 0; j < 8; j++)
            #pragma unroll
            for (int i = 0; i < 4; i++) {
                sacc[j][2 * i]     = fast_exp2(sacc[j][2 * i]     - mrun[i]);
                sacc[j][2 * i + 1] = fast_exp2(sacc[j][2 * i + 1] - mrun[i]);
                l[i] += sacc[j][2 * i] + sacc[j][2 * i + 1];
            }
        #pragma unroll
        for (int i = 0; i < 4; i++) {
            l[i] += __shfl_xor_sync(0xffffffffu, l[i], 1);
            l[i] += __shfl_xor_sync(0xffffffffu, l[i], 2);
            lrun[i] = lrun[i] * al[i] + l[i];
        }

        // ---- rescale O ----
        #pragma unroll
        for (int j = 0; j < 8; j++)
            #pragma unroll
            for (int i = 0; i < 4; i++) {
                o[j][2 * i]     *= al[i];
                o[j][2 * i + 1] *= al[i];
            }

        // ---- P -> warp pad (column-pair permuted; 2x STS.32 per j per row) ----
        #pragma unroll
        for (int j = 0; j < 8; j++) {
            const int cbase = j * 8;
            #pragma unroll
            for (int i = 0; i < 4; i++) {
                const int rw = (g + 8 * i) * PSS + cbase;
                PwU[rw + pe] = f2tf(sacc[j][2 * i]);
                PwU[rw + po] = f2tf(sacc[j][2 * i + 1]);
            }
        }
        __syncwarp();

        // ---- O += P @ V : LDS.64 A and B fragments ----
        #pragma unroll
        for (int kc = 0; kc < 8; kc++) {
            const int pc = kc * 8 + 2 * b;
            const uint2 p0 = *(const uint2*)&PwU[ g       * PSS + pc];
            const uint2 p1 = *(const uint2*)&PwU[(g +  8) * PSS + pc];
            const uint2 p2 = *(const uint2*)&PwU[(g + 16) * PSS + pc];
            const uint2 p3 = *(const uint2*)&PwU[(g + 24) * PSS + pc];
            uint32_t pa0[4] = {p0.x, p1.x, p0.y, p1.y};
            uint32_t pa1[4] = {p2.x, p3.x, p2.y, p3.y};
            const int vbase = kc * VGR + b * VRP;
            #pragma unroll
            for (int j = 0; j < 8; j++) {
                const uint2 vv = *(const uint2*)&VsU[vbase + (j * 8 + g) * 2];
                mma_tf32(&o[j][0], pa0, vv.x, vv.y);
                mma_tf32(&o[j][4], pa1, vv.x, vv.y);
            }
        }
        __syncwarp();  // P reads done before next iter overwrites pad

        __syncthreads();  // all stage reads done before re-fill
    }

    // ---- epilogue: normalize + store ----
    {
        float inv[4];
        #pragma unroll
        for (int i = 0; i < 4; i++) inv[i] = (lrun[i] > 0.0f) ? (1.0f / lrun[i]) : 0.0f;
        float* orow = out + ((size_t)head * QLEN + q0 + r0) * DIM;
        #pragma unroll
        for (int j = 0; j < 8; j++) {
            const int col = j * 8 + 2 * b;
            *(float2*)&orow[ 0 * DIM + col] = make_float2(o[j][0] * inv[0], o[j][1] * inv[0]);
            *(float2*)&orow[ 8 * DIM + col] = make_float2(o[j][2] * inv[1], o[j][3] * inv[1]);
            *(float2*)&orow[16 * DIM + col] = make_float2(o[j][4] * inv[2], o[j][5] * inv[2]);
            *(float2*)&orow[24 * DIM + col] = make_float2(o[j][6] * inv[3], o[j][7] * inv[3]);
        }
    }
}

extern "C" void kernel_launch(void* const* d_in, const int* in_sizes, int n_in,
                              void* d_out, int out_size)
{
    const float* qs = (const float*)d_in[0];
    const float* ks = (const float*)d_in[1];
    const float* vs = (const float*)d_in[2];
    const unsigned int* maskw = (const unsigned int*)d_in[3];
    float* out = (float*)d_out;

    // prepass: tf32-round + permute K,V (1,048,576 uint4s each)
    kv_permute<<<4096, 256>>>(ks, vs);

    cudaFuncSetAttribute(fa_hmma_v64, cudaFuncAttributeMaxDynamicSharedMemorySize, SMEM_BYTES);
    dim3 grid(QLEN / BQ, NHEAD);
    fa_hmma_v64<<<grid, NTHREADS, SMEM_BYTES>>>(qs, maskw, out);
}

// round 12
// speedup vs baseline: 1.0199x; 1.0199x over previous
#include <cuda_runtime.h>
#include <cuda_fp16.h>
#include <cstdint>

#define NHEAD 16
#define QLEN  4096
#define KLEN  4096
#define DIM   64
#define BQ    128
#define BK    64
#define NTHREADS 128
#define NITER (KLEN / BK)

#define KSS 68   // K tile stride (floats): B-frag loads conflict-free
#define VSS 72   // V tile stride: conflict-free
#define PSS 68   // P pad stride: A-frag loads conflict-free

#define STAGE_K_FLOATS (64 * KSS)                      // 4352
#define STAGE_FLOATS   (STAGE_K_FLOATS + 64 * VSS)     // 8960
#define PS_OFF         (2 * STAGE_FLOATS)              // 17920
#define SMEM_FLOATS    (PS_OFF + 4 * 32 * PSS)         // 26624
#define SMEM_BYTES     (SMEM_FLOATS * 4)               // 106496

// pre-rounded tf32 K/V scratch (static __device__: allocation-free)
__device__ uint32_t g_Kr[NHEAD * KLEN * DIM];
__device__ uint32_t g_Vr[NHEAD * KLEN * DIM];

__device__ __forceinline__ uint32_t f2tf(float x) {
    uint32_t r; asm("cvt.rna.tf32.f32 %0, %1;" : "=r"(r) : "f"(x)); return r;
}
__device__ __forceinline__ float fast_exp2(float x) {
    float y; asm("ex2.approx.ftz.f32 %0, %1;" : "=f"(y) : "f"(x)); return y;
}
__device__ __forceinline__ uint32_t smem_u32(const void* p) {
    uint32_t a;
    asm("{ .reg .u64 t; cvta.to.shared.u64 t, %1; cvt.u32.u64 %0, t; }" : "=r"(a) : "l"(p));
    return a;
}
__device__ __forceinline__ void cp16(uint32_t dst, const void* src) {
    asm volatile("cp.async.ca.shared.global [%0], [%1], 16;" :: "r"(dst), "l"(src) : "memory");
}
#define CP_COMMIT() asm volatile("cp.async.commit_group;" ::: "memory")
#define CP_WAIT1()  asm volatile("cp.async.wait_group 1;" ::: "memory")

// D(16x8,f32) += A(16x8,tf32) * B(8x8,tf32)   [row.col]
__device__ __forceinline__ void mma_tf32(float* d, const uint32_t* a,
                                         uint32_t b0, uint32_t b1) {
    asm volatile(
        "mma.sync.aligned.m16n8k8.row.col.f32.tf32.tf32.f32 "
        "{%0,%1,%2,%3}, {%4,%5,%6,%7}, {%8,%9}, {%0,%1,%2,%3};"
        : "+f"(d[0]), "+f"(d[1]), "+f"(d[2]), "+f"(d[3])
        : "r"(a[0]), "r"(a[1]), "r"(a[2]), "r"(a[3]), "r"(b0), "r"(b1));
}

// ---- prepass: round K,V to tf32 (rna) once ----
extern "C" __global__ void __launch_bounds__(256)
kv_round(const float* __restrict__ ks, const float* __restrict__ vs)
{
    const size_t i = (size_t)blockIdx.x * blockDim.x + threadIdx.x;  // float4 index
    float4 k = ((const float4*)ks)[i];
    ((uint4*)g_Kr)[i] = make_uint4(f2tf(k.x), f2tf(k.y), f2tf(k.z), f2tf(k.w));
    float4 v = ((const float4*)vs)[i];
    ((uint4*)g_Vr)[i] = make_uint4(f2tf(v.x), f2tf(v.y), f2tf(v.z), f2tf(v.w));
}

extern "C" __global__ void __launch_bounds__(NTHREADS, 2)
fa_hmma_hx2(const float* __restrict__ qs, const unsigned int* __restrict__ maskw,
            float* __restrict__ out)
{
    extern __shared__ float sm[];
    const uint32_t sb = smem_u32(sm);

    const int tid  = threadIdx.x;
    const int w    = tid >> 5;
    const int lane = tid & 31;
    const int g    = lane >> 2;   // row within 8
    const int b    = lane & 3;    // k/col selector

    uint32_t* PwU = (uint32_t*)(sm + PS_OFF) + w * 32 * PSS;  // warp P pad [32][PSS]

    const int head = blockIdx.y;
    const int q0   = blockIdx.x * BQ;
    const int r0   = w * 32 + g;             // rows r0, +8, +16, +24

    const float qscale = 0.125f * 1.44269504088896340736f;  // 1/sqrt(D)*log2(e)
    const float* qg = qs + ((size_t)head * QLEN + q0) * DIM;
    const uint32_t* kg = g_Kr + (size_t)head * KLEN * DIM;
    const uint32_t* vg = g_Vr + (size_t)head * KLEN * DIM;

    const int srow = tid >> 4;          // cp.async row base
    const int scol = (tid & 15) * 4;    // cp.async col (floats)

    // ---- prologue: prefetch stage 0 ----
    {
        #pragma unroll
        for (int i = 0; i < 8; i++) {
            const int r = srow + 8 * i;
            cp16(sb + (r * KSS + scol) * 4, kg + (size_t)r * DIM + scol);
            cp16(sb + (STAGE_K_FLOATS + r * VSS + scol) * 4, vg + (size_t)r * DIM + scol);
        }
        CP_COMMIT();
    }

    // ---- persistent Q A-fragments ----
    uint32_t qa[8][8];
    {
        const float* q0p = qg + (size_t)r0 * DIM;
        const float* q1p = q0p + 8 * DIM;
        const float* q2p = q0p + 16 * DIM;
        const float* q3p = q0p + 24 * DIM;
        #pragma unroll
        for (int c = 0; c < 8; c++) {
            const int k0c = c * 8 + b;
            qa[c][0] = f2tf(q0p[k0c]     * qscale);
            qa[c][1] = f2tf(q1p[k0c]     * qscale);
            qa[c][2] = f2tf(q0p[k0c + 4] * qscale);
            qa[c][3] = f2tf(q1p[k0c + 4] * qscale);
            qa[c][4] = f2tf(q2p[k0c]     * qscale);
            qa[c][5] = f2tf(q3p[k0c]     * qscale);
            qa[c][6] = f2tf(q2p[k0c + 4] * qscale);
            qa[c][7] = f2tf(q3p[k0c + 4] * qscale);
        }
    }

    float o[8][8];
    #pragma unroll
    for (int j = 0; j < 8; j++)
        #pragma unroll
        for (int e = 0; e < 8; e++) o[j][e] = 0.0f;
    float mrun[4] = {-1e30f, -1e30f, -1e30f, -1e30f};
    float lrun[4] = {0.0f, 0.0f, 0.0f, 0.0f};

    for (int it = 0; it < NITER; it++) {
        const int k0 = it * BK;
        const int stage = it & 1;
        const int kb = k0 >> 2;

        // ---- prefetch next tile into other stage ----
        {
            const int knx = (it + 1 < NITER ? it + 1 : it) * BK;
            const uint32_t sbase = sb + ((1 - stage) * STAGE_FLOATS) * 4;
            #pragma unroll
            for (int i = 0; i < 8; i++) {
                const int r = srow + 8 * i;
                cp16(sbase + (r * KSS + scol) * 4, kg + (size_t)(knx + r) * DIM + scol);
                cp16(sbase + (STAGE_K_FLOATS + r * VSS + scol) * 4,
                     vg + (size_t)(knx + r) * DIM + scol);
            }
            CP_COMMIT();
        }
        CP_WAIT1();          // this stage's data landed
        __syncthreads();     // all threads' data visible; prev-iter reads done

        const uint32_t* KsU = (const uint32_t*)(sm + stage * STAGE_FLOATS);
        const uint32_t* VsU = KsU + STAGE_K_FLOATS;

        // ---- S = Q @ K^T : B fragment shared by both A row-blocks ----
        float sacc[8][8];
        #pragma unroll
        for (int j = 0; j < 8; j++)
            #pragma unroll
            for (int e = 0; e < 8; e++) sacc[j][e] = 0.0f;

        #pragma unroll
        for (int c = 0; c < 8; c++) {
            #pragma unroll
            for (int j = 0; j < 8; j++) {
                const uint32_t* kp = &KsU[(j * 8 + g) * KSS + c * 8 + b];
                const uint32_t kb0 = kp[0], kb1 = kp[4];
                mma_tf32(&sacc[j][0], &qa[c][0], kb0, kb1);
                mma_tf32(&sacc[j][4], &qa[c][4], kb0, kb1);
            }
        }

        // ---- mask (robust word-of-4; all-true -> never taken) ----
        #pragma unroll
        for (int j = 0; j < 8; j++) {
            if (maskw[kb + 2 * j + (b >> 1)] == 0u) {
                #pragma unroll
                for (int e = 0; e < 8; e++) sacc[j][e] = -1e30f;
            }
        }

        // ---- online softmax (log2 domain), 4 row-blocks ----
        float m[4] = {-1e30f, -1e30f, -1e30f, -1e30f};
        #pragma unroll
        for (int j = 0; j < 8; j++)
            #pragma unroll
            for (int i = 0; i < 4; i++)
                m[i] = fmaxf(m[i], fmaxf(sacc[j][2 * i], sacc[j][2 * i + 1]));
        #pragma unroll
        for (int i = 0; i < 4; i++) {
            m[i] = fmaxf(m[i], __shfl_xor_sync(0xffffffffu, m[i], 1));
            m[i] = fmaxf(m[i], __shfl_xor_sync(0xffffffffu, m[i], 2));
        }
        float al[4];
        #pragma unroll
        for (int i = 0; i < 4; i++) {
            const float mn = fmaxf(mrun[i], m[i]);
            al[i] = fast_exp2(mrun[i] - mn);   // f32 ex2: only 4/iter, no bias drift
            mrun[i] = mn;
        }

        // exp via packed f16x2 MUFU (2 exps/op). f16 mantissa (10b) is a subset
        // of tf32 (11b), so unpacked p is tf32-exact: no f2tf needed on P.
        float l[4] = {0.0f, 0.0f, 0.0f, 0.0f};
        #pragma unroll
        for (int j = 0; j < 8; j++) {
            #pragma unroll
            for (int i = 0; i < 4; i++) {
                __half2 h = h2exp2(__floats2half2_rn(
                    sacc[j][2 * i] - mrun[i], sacc[j][2 * i + 1] - mrun[i]));
                float2 p = __half22float2(h);
                sacc[j][2 * i]     = p.x;
                sacc[j][2 * i + 1] = p.y;
                l[i] += p.x + p.y;
            }
        }
        #pragma unroll
        for (int i = 0; i < 4; i++) {
            l[i] += __shfl_xor_sync(0xffffffffu, l[i], 1);
            l[i] += __shfl_xor_sync(0xffffffffu, l[i], 2);
            lrun[i] = lrun[i] * al[i] + l[i];
        }

        // ---- rescale O ----
        #pragma unroll
        for (int j = 0; j < 8; j++)
            #pragma unroll
            for (int i = 0; i < 4; i++) {
                o[j][2 * i]     *= al[i];
                o[j][2 * i + 1] *= al[i];
            }

        // ---- P -> warp-private smem pad (tf32-exact f32 bits) ----
        #pragma unroll
        for (int j = 0; j < 8; j++) {
            const int col = j * 8 + 2 * b;
            *(uint2*)&PwU[ g       * PSS + col] =
                make_uint2(__float_as_uint(sacc[j][0]), __float_as_uint(sacc[j][1]));
            *(uint2*)&PwU[(g +  8) * PSS + col] =
                make_uint2(__float_as_uint(sacc[j][2]), __float_as_uint(sacc[j][3]));
            *(uint2*)&PwU[(g + 16) * PSS + col] =
                make_uint2(__float_as_uint(sacc[j][4]), __float_as_uint(sacc[j][5]));
            *(uint2*)&PwU[(g + 24) * PSS + col] =
                make_uint2(__float_as_uint(sacc[j][6]), __float_as_uint(sacc[j][7]));
        }
        __syncwarp();

        // ---- O += P @ V : B fragment shared by both A row-blocks ----
        #pragma unroll
        for (int kc = 0; kc < 8; kc++) {
            uint32_t pa0[4], pa1[4];
            const int kcol = kc * 8 + b;
            pa0[0] = PwU[ g       * PSS + kcol];
            pa0[1] = PwU[(g +  8) * PSS + kcol];
            pa0[2] = PwU[ g       * PSS + kcol + 4];
            pa0[3] = PwU[(g +  8) * PSS + kcol + 4];
            pa1[0] = PwU[(g + 16) * PSS + kcol];
            pa1[1] = PwU[(g + 24) * PSS + kcol];
            pa1[2] = PwU[(g + 16) * PSS + kcol + 4];
            pa1[3] = PwU[(g + 24) * PSS + kcol + 4];
            #pragma unroll
            for (int j = 0; j < 8; j++) {
                const uint32_t v0 = VsU[(kc * 8 + b)     * VSS + j * 8 + g];
                const uint32_t v1 = VsU[(kc * 8 + b + 4) * VSS + j * 8 + g];
                mma_tf32(&o[j][0], pa0, v0, v1);
                mma_tf32(&o[j][4], pa1, v0, v1);
            }
        }
        __syncwarp();  // Pw reads done before next iter's overwrite

        __syncthreads();  // everyone done reading this stage before it is re-filled
    }

    // ---- epilogue: normalize + store ----
    {
        float inv[4];
        #pragma unroll
        for (int i = 0; i < 4; i++) inv[i] = (lrun[i] > 0.0f) ? (1.0f / lrun[i]) : 0.0f;
        float* orow = out + ((size_t)head * QLEN + q0 + r0) * DIM;
        #pragma unroll
        for (int j = 0; j < 8; j++) {
            const int col = j * 8 + 2 * b;
            *(float2*)&orow[ 0 * DIM + col] = make_float2(o[j][0] * inv[0], o[j][1] * inv[0]);
            *(float2*)&orow[ 8 * DIM + col] = make_float2(o[j][2] * inv[1], o[j][3] * inv[1]);
            *(float2*)&orow[16 * DIM + col] = make_float2(o[j][4] * inv[2], o[j][5] * inv[2]);
            *(float2*)&orow[24 * DIM + col] = make_float2(o[j][6] * inv[3], o[j][7] * inv[3]);
        }
    }
}

extern "C" void kernel_launch(void* const* d_in, const int* in_sizes, int n_in,
                              void* d_out, int out_size)
{
    const float* qs = (const float*)d_in[0];
    const float* ks = (const float*)d_in[1];
    const float* vs = (const float*)d_in[2];
    const unsigned int* maskw = (const unsigned int*)d_in[3];
    float* out = (float*)d_out;

    // prepass: round K,V to tf32 into static scratch
    const int total4 = NHEAD * KLEN * DIM / 4;
    kv_round<<<total4 / 256, 256>>>(ks, vs);

    cudaFuncSetAttribute(fa_hmma_hx2, cudaFuncAttributeMaxDynamicSharedMemorySize, SMEM_BYTES);
    dim3 grid(QLEN / BQ, NHEAD);
    fa_hmma_hx2<<<grid, NTHREADS, SMEM_BYTES>>>(qs, maskw, out);
}

// round 13
// speedup vs baseline: 1.9485x; 1.9104x over previous
#include <cuda_runtime.h>
#include <cuda_fp16.h>
#include <cstdint>

#define NHEAD 16
#define QLEN  4096
#define KLEN  4096
#define DIM   64
#define BQ    128
#define BK    64
#define NTHREADS 128
#define NITER (KLEN / BK)

// strides in 4-byte words (each word = half2)
#define KSW 36   // K tile row stride: frag loads bank 4g+b (CF)
#define VSW 72   // V kp-row stride: frag loads bank 8b+g (CF)
#define PSW 36   // P pad row stride: stores/loads bank 4g+b (CF)

#define STAGE_K_WORDS (64 * KSW)                  // 2304
#define STAGE_V_WORDS (32 * VSW)                  // 2304
#define STAGE_WORDS   (STAGE_K_WORDS + STAGE_V_WORDS)  // 4608
#define PS_OFF        (2 * STAGE_WORDS)           // 9216
#define SMEM_WORDS    (PS_OFF + 4 * 32 * PSW)     // 13824
#define SMEM_BYTES    (SMEM_WORDS * 4)            // 55296

// fp16 K/V scratch (static __device__: allocation-free)
// g_Kh: [h][key n][dim k] halves, row = 32 words; word (n, w) = {K[n][2w], K[n][2w+1]}
// g_Vh: [h][kp][n] half2;  word (kp, n) = {V[2kp][n], V[2kp+1][n]}, row = 64 words
__device__ uint32_t g_Kh[NHEAD * KLEN * 32];
__device__ uint32_t g_Vh[NHEAD * (KLEN / 2) * 64];

__device__ __forceinline__ float fast_exp2(float x) {
    float y; asm("ex2.approx.ftz.f32 %0, %1;" : "=f"(y) : "f"(x)); return y;
}
__device__ __forceinline__ uint32_t smem_u32(const void* p) {
    uint32_t a;
    asm("{ .reg .u64 t; cvta.to.shared.u64 t, %1; cvt.u32.u64 %0, t; }" : "=r"(a) : "l"(p));
    return a;
}
__device__ __forceinline__ void cp16(uint32_t dst, const void* src) {
    asm volatile("cp.async.ca.shared.global [%0], [%1], 16;" :: "r"(dst), "l"(src) : "memory");
}
#define CP_COMMIT() asm volatile("cp.async.commit_group;" ::: "memory")
#define CP_WAIT1()  asm volatile("cp.async.wait_group 1;" ::: "memory")

__device__ __forceinline__ uint32_t packh2(float a, float b) {
    __half2 h = __floats2half2_rn(a, b);
    return *reinterpret_cast<uint32_t*>(&h);
}

// D(16x8,f32) += A(16x16,f16) * B(16x8,f16)   [row.col]
__device__ __forceinline__ void mma_f16(float* d, const uint32_t* a,
                                        uint32_t b0, uint32_t b1) {
    asm volatile(
        "mma.sync.aligned.m16n8k16.row.col.f32.f16.f16.f32 "
        "{%0,%1,%2,%3}, {%4,%5,%6,%7}, {%8,%9}, {%0,%1,%2,%3};"
        : "+f"(d[0]), "+f"(d[1]), "+f"(d[2]), "+f"(d[3])
        : "r"(a[0]), "r"(a[1]), "r"(a[2]), "r"(a[3]), "r"(b0), "r"(b1));
}

// ---- prepass: convert K,V to fp16 in MMA-friendly layouts ----
extern "C" __global__ void __launch_bounds__(256)
kv_half(const float* __restrict__ ks, const float* __restrict__ vs)
{
    const int i = blockIdx.x * 256 + threadIdx.x;   // 524288 threads

    // K: thread converts 8 dims of one key row -> uint4 (8 halves)
    {
        const int h = i >> 15;                      // 32768 chunks/head
        const int rem = i & 32767;
        const int n = rem >> 3, c = rem & 7;        // key, chunk of 8 dims
        const float* src = ks + ((size_t)h * KLEN + n) * DIM + c * 8;
        float4 v0 = *(const float4*)(src);
        float4 v1 = *(const float4*)(src + 4);
        uint4 r;
        r.x = packh2(v0.x, v0.y); r.y = packh2(v0.z, v0.w);
        r.z = packh2(v1.x, v1.y); r.w = packh2(v1.z, v1.w);
        *(uint4*)(g_Kh + ((size_t)h * KLEN + n) * 32 + c * 4) = r;
    }
    // V: thread makes 4 half2 words {V[2kp][n],V[2kp+1][n]} for n..n+3
    {
        const int h = i >> 15;
        const int rem = i & 32767;
        const int kp = rem >> 4, c = rem & 15;
        const int n0 = c * 4;
        const float* srcA = vs + ((size_t)h * KLEN + 2 * kp) * DIM + n0;
        const float* srcB = srcA + DIM;
        float4 a = *(const float4*)srcA;
        float4 bb = *(const float4*)srcB;
        uint4 r;
        r.x = packh2(a.x, bb.x); r.y = packh2(a.y, bb.y);
        r.z = packh2(a.z, bb.z); r.w = packh2(a.w, bb.w);
        *(uint4*)(g_Vh + ((size_t)h * (KLEN / 2) + kp) * 64 + n0) = r;
    }
}

extern "C" __global__ void __launch_bounds__(NTHREADS, 2)
fa_hmma_f16(const float* __restrict__ qs, const unsigned int* __restrict__ maskw,
            float* __restrict__ out)
{
    extern __shared__ uint32_t smw[];
    const uint32_t sb = smem_u32(smw);

    const int tid  = threadIdx.x;
    const int w    = tid >> 5;
    const int lane = tid & 31;
    const int g    = lane >> 2;   // row within 8
    const int b    = lane & 3;    // k/col selector

    uint32_t* PwU = smw + PS_OFF + w * 32 * PSW;  // warp P pad [32 rows][PSW]

    const int head = blockIdx.y;
    const int q0   = blockIdx.x * BQ;
    const int r0   = w * 32 + g;             // q rows r0, +8, +16, +24

    const float qscale = 0.125f * 1.44269504088896340736f;  // 1/sqrt(D)*log2(e)
    const float* qg = qs + ((size_t)head * QLEN + q0) * DIM;
    const uint32_t* kg = g_Kh + (size_t)head * KLEN * 32;
    const uint32_t* vg = g_Vh + (size_t)head * (KLEN / 2) * 64;

    // ---- prologue: prefetch stage 0 (K rows 128B, V kp-rows 256B) ----
    {
        #pragma unroll
        for (int i = 0; i < 4; i++) {
            const int idx = tid + NTHREADS * i;
            const int kr = idx >> 3, kp8 = (idx & 7) * 4;         // K: row, word chunk
            cp16(sb + (kr * KSW + kp8) * 4, kg + (size_t)kr * 32 + kp8);
            const int vr = idx >> 4, vp = (idx & 15) * 4;         // V: kp-row, word chunk
            cp16(sb + (STAGE_K_WORDS + vr * VSW + vp) * 4, vg + (size_t)vr * 64 + vp);
        }
        CP_COMMIT();
    }

    // ---- persistent Q A-fragments (fp16 pairs; 4 ktiles x 8 regs) ----
    uint32_t qa[4][8];
    {
        const float* q0p = qg + (size_t)r0 * DIM;
        const float* q1p = q0p + 8 * DIM;
        const float* q2p = q0p + 16 * DIM;
        const float* q3p = q0p + 24 * DIM;
        #pragma unroll
        for (int kc = 0; kc < 4; kc++) {
            const int kA = kc * 16 + 2 * b;        // pair cols kA,kA+1
            const int kB = kA + 8;                 // pair cols kB,kB+1
            qa[kc][0] = packh2(q0p[kA] * qscale, q0p[kA + 1] * qscale);
            qa[kc][1] = packh2(q1p[kA] * qscale, q1p[kA + 1] * qscale);
            qa[kc][2] = packh2(q0p[kB] * qscale, q0p[kB + 1] * qscale);
            qa[kc][3] = packh2(q1p[kB] * qscale, q1p[kB + 1] * qscale);
            qa[kc][4] = packh2(q2p[kA] * qscale, q2p[kA + 1] * qscale);
            qa[kc][5] = packh2(q3p[kA] * qscale, q3p[kA + 1] * qscale);
            qa[kc][6] = packh2(q2p[kB] * qscale, q2p[kB + 1] * qscale);
            qa[kc][7] = packh2(q3p[kB] * qscale, q3p[kB + 1] * qscale);
        }
    }

    float o[8][8];
    #pragma unroll
    for (int j = 0; j < 8; j++)
        #pragma unroll
        for (int e = 0; e < 8; e++) o[j][e] = 0.0f;
    float mrun[4] = {-1e30f, -1e30f, -1e30f, -1e30f};
    float lrun[4] = {0.0f, 0.0f, 0.0f, 0.0f};

    for (int it = 0; it < NITER; it++) {
        const int k0 = it * BK;
        const int stage = it & 1;
        const int kb = k0 >> 2;

        // ---- prefetch next tile into other stage ----
        {
            const int knx = (it + 1 < NITER ? it + 1 : it) * BK;
            const uint32_t sbase = sb + ((1 - stage) * STAGE_WORDS) * 4;
            const uint32_t* kgn = kg + (size_t)knx * 32;
            const uint32_t* vgn = vg + (size_t)(knx >> 1) * 64;
            #pragma unroll
            for (int i = 0; i < 4; i++) {
                const int idx = tid + NTHREADS * i;
                const int kr = idx >> 3, kp8 = (idx & 7) * 4;
                cp16(sbase + (kr * KSW + kp8) * 4, kgn + (size_t)kr * 32 + kp8);
                const int vr = idx >> 4, vp = (idx & 15) * 4;
                cp16(sbase + (STAGE_K_WORDS + vr * VSW + vp) * 4, vgn + (size_t)vr * 64 + vp);
            }
            CP_COMMIT();
        }
        CP_WAIT1();          // this stage's data landed
        __syncthreads();     // all threads' data visible; prev-iter reads done

        const uint32_t* KsU = smw + stage * STAGE_WORDS;
        const uint32_t* VsU = KsU + STAGE_K_WORDS;

        // ---- S = Q @ K^T : fp16 m16n8k16, B frag shared by both row-blocks ----
        float sacc[8][8];
        #pragma unroll
        for (int j = 0; j < 8; j++)
            #pragma unroll
            for (int e = 0; e < 8; e++) sacc[j][e] = 0.0f;

        #pragma unroll
        for (int kc = 0; kc < 4; kc++) {
            #pragma unroll
            for (int j = 0; j < 8; j++) {
                const uint32_t* kp = &KsU[(j * 8 + g) * KSW + kc * 8 + b];
                const uint32_t kb0 = kp[0], kb1 = kp[4];
                mma_f16(&sacc[j][0], &qa[kc][0], kb0, kb1);
                mma_f16(&sacc[j][4], &qa[kc][4], kb0, kb1);
            }
        }

        // ---- mask (robust word-of-4; all-true -> never taken) ----
        #pragma unroll
        for (int j = 0; j < 8; j++) {
            if (maskw[kb + 2 * j + (b >> 1)] == 0u) {
                #pragma unroll
                for (int e = 0; e < 8; e++) sacc[j][e] = -1e30f;
            }
        }

        // ---- online softmax (log2 domain), 4 row-blocks ----
        float m[4] = {-1e30f, -1e30f, -1e30f, -1e30f};
        #pragma unroll
        for (int j = 0; j < 8; j++)
            #pragma unroll
            for (int i = 0; i < 4; i++)
                m[i] = fmaxf(m[i], fmaxf(sacc[j][2 * i], sacc[j][2 * i + 1]));
        #pragma unroll
        for (int i = 0; i < 4; i++) {
            m[i] = fmaxf(m[i], __shfl_xor_sync(0xffffffffu, m[i], 1));
            m[i] = fmaxf(m[i], __shfl_xor_sync(0xffffffffu, m[i], 2));
        }
        float al[4];
        #pragma unroll
        for (int i = 0; i < 4; i++) {
            const float mn = fmaxf(mrun[i], m[i]);
            al[i] = fast_exp2(mrun[i] - mn);   // f32 ex2 for the rescale factor
            mrun[i] = mn;
        }

        // packed f16x2 exp; result half2 = {p(col 2b), p(col 2b+1)} = P A-frag pair
        float l[4] = {0.0f, 0.0f, 0.0f, 0.0f};
        uint32_t ph[8][4];
        #pragma unroll
        for (int j = 0; j < 8; j++) {
            #pragma unroll
            for (int i = 0; i < 4; i++) {
                __half2 h = h2exp2(__floats2half2_rn(
                    sacc[j][2 * i] - mrun[i], sacc[j][2 * i + 1] - mrun[i]));
                ph[j][i] = *reinterpret_cast<uint32_t*>(&h);
                float2 p = __half22float2(h);
                l[i] += p.x + p.y;
            }
        }
        #pragma unroll
        for (int i = 0; i < 4; i++) {
            l[i] += __shfl_xor_sync(0xffffffffu, l[i], 1);
            l[i] += __shfl_xor_sync(0xffffffffu, l[i], 2);
            lrun[i] = lrun[i] * al[i] + l[i];
        }

        // ---- rescale O ----
        #pragma unroll
        for (int j = 0; j < 8; j++)
            #pragma unroll
            for (int i = 0; i < 4; i++) {
                o[j][2 * i]     *= al[i];
                o[j][2 * i + 1] *= al[i];
            }

        // ---- P -> warp pad: word (row g+8i, pair-col 4j+b) ----
        #pragma unroll
        for (int j = 0; j < 8; j++) {
            const int col = 4 * j + b;
            PwU[ g       * PSW + col] = ph[j][0];
            PwU[(g +  8) * PSW + col] = ph[j][1];
            PwU[(g + 16) * PSW + col] = ph[j][2];
            PwU[(g + 24) * PSW + col] = ph[j][3];
        }
        __syncwarp();

        // ---- O += P @ V : fp16 m16n8k16 ----
        #pragma unroll
        for (int kc = 0; kc < 4; kc++) {
            uint32_t pa0[4], pa1[4];
            const int c0 = kc * 8 + b;
            pa0[0] = PwU[ g       * PSW + c0];
            pa0[1] = PwU[(g +  8) * PSW + c0];
            pa0[2] = PwU[ g       * PSW + c0 + 4];
            pa0[3] = PwU[(g +  8) * PSW + c0 + 4];
            pa1[0] = PwU[(g + 16) * PSW + c0];
            pa1[1] = PwU[(g + 24) * PSW + c0];
            pa1[2] = PwU[(g + 16) * PSW + c0 + 4];
            pa1[3] = PwU[(g + 24) * PSW + c0 + 4];
            #pragma unroll
            for (int j = 0; j < 8; j++) {
                const uint32_t v0 = VsU[(kc * 8 + b)     * VSW + j * 8 + g];
                const uint32_t v1 = VsU[(kc * 8 + b + 4) * VSW + j * 8 + g];
                mma_f16(&o[j][0], pa0, v0, v1);
                mma_f16(&o[j][4], pa1, v0, v1);
            }
        }
        __syncwarp();  // P reads done before next iter's overwrite

        __syncthreads();  // everyone done reading this stage before it is re-filled
    }

    // ---- epilogue: normalize + store ----
    {
        float inv[4];
        #pragma unroll
        for (int i = 0; i < 4; i++) inv[i] = (lrun[i] > 0.0f) ? (1.0f / lrun[i]) : 0.0f;
        float* orow = out + ((size_t)head * QLEN + q0 + r0) * DIM;
        #pragma unroll
        for (int j = 0; j < 8; j++) {
            const int col = j * 8 + 2 * b;
            *(float2*)&orow[ 0 * DIM + col] = make_float2(o[j][0] * inv[0], o[j][1] * inv[0]);
            *(float2*)&orow[ 8 * DIM + col] = make_float2(o[j][2] * inv[1], o[j][3] * inv[1]);
            *(float2*)&orow[16 * DIM + col] = make_float2(o[j][4] * inv[2], o[j][5] * inv[2]);
            *(float2*)&orow[24 * DIM + col] = make_float2(o[j][6] * inv[3], o[j][7] * inv[3]);
        }
    }
}

extern "C" void kernel_launch(void* const* d_in, const int* in_sizes, int n_in,
                              void* d_out, int out_size)
{
    const float* qs = (const float*)d_in[0];
    const float* ks = (const float*)d_in[1];
    const float* vs = (const float*)d_in[2];
    const unsigned int* maskw = (const unsigned int*)d_in[3];
    float* out = (float*)d_out;

    // prepass: fp16-convert K,V into MMA-pair layouts (524288 threads)
    kv_half<<<2048, 256>>>(ks, vs);

    cudaFuncSetAttribute(fa_hmma_f16, cudaFuncAttributeMaxDynamicSharedMemorySize, SMEM_BYTES);
    dim3 grid(QLEN / BQ, NHEAD);
    fa_hmma_f16<<<grid, NTHREADS, SMEM_BYTES>>>(qs, maskw, out);
}

// round 14
// speedup vs baseline: 2.1170x; 1.0865x over previous
#include <cuda_runtime.h>
#include <cuda_fp16.h>
#include <cstdint>

#define NHEAD 16
#define QLEN  4096
#define KLEN  4096
#define DIM   64
#define BQ    128
#define BK    64
#define NTHREADS 128
#define NITER (KLEN / BK)

// strides in 4-byte words (each word = half2)
#define KSW 36   // K tile row stride: frag loads bank 4g+b (CF)
#define VSW 72   // V kp-row stride: frag loads bank 8b+g (CF)

#define STAGE_K_WORDS (64 * KSW)                  // 2304
#define STAGE_V_WORDS (32 * VSW)                  // 2304
#define STAGE_WORDS   (STAGE_K_WORDS + STAGE_V_WORDS)  // 4608
#define SMEM_WORDS    (2 * STAGE_WORDS)           // 9216
#define SMEM_BYTES    (SMEM_WORDS * 4)            // 36864

#define ONESH2 0x3C003C00u   // half2 {1.0, 1.0}

// fp16 K/V scratch (static __device__: allocation-free)
// g_Kh: [h][key n][dim k] halves, row = 32 words; word (n, w) = {K[n][2w], K[n][2w+1]}
// g_Vh: [h][kp][n] half2;  word (kp, n) = {V[2kp][n], V[2kp+1][n]}, row = 64 words
__device__ uint32_t g_Kh[NHEAD * KLEN * 32];
__device__ uint32_t g_Vh[NHEAD * (KLEN / 2) * 64];

__device__ __forceinline__ float fast_exp2(float x) {
    float y; asm("ex2.approx.ftz.f32 %0, %1;" : "=f"(y) : "f"(x)); return y;
}
__device__ __forceinline__ uint32_t smem_u32(const void* p) {
    uint32_t a;
    asm("{ .reg .u64 t; cvta.to.shared.u64 t, %1; cvt.u32.u64 %0, t; }" : "=r"(a) : "l"(p));
    return a;
}
__device__ __forceinline__ void cp16(uint32_t dst, const void* src) {
    asm volatile("cp.async.ca.shared.global [%0], [%1], 16;" :: "r"(dst), "l"(src) : "memory");
}
#define CP_COMMIT() asm volatile("cp.async.commit_group;" ::: "memory")
#define CP_WAIT1()  asm volatile("cp.async.wait_group 1;" ::: "memory")

__device__ __forceinline__ uint32_t packh2(float a, float b) {
    __half2 h = __floats2half2_rn(a, b);
    return *reinterpret_cast<uint32_t*>(&h);
}

// D(16x8,f32) += A(16x16,f16) * B(16x8,f16)   [row.col]
__device__ __forceinline__ void mma_f16(float* d, const uint32_t* a,
                                        uint32_t b0, uint32_t b1) {
    asm volatile(
        "mma.sync.aligned.m16n8k16.row.col.f32.f16.f16.f32 "
        "{%0,%1,%2,%3}, {%4,%5,%6,%7}, {%8,%9}, {%0,%1,%2,%3};"
        : "+f"(d[0]), "+f"(d[1]), "+f"(d[2]), "+f"(d[3])
        : "r"(a[0]), "r"(a[1]), "r"(a[2]), "r"(a[3]), "r"(b0), "r"(b1));
}

// ---- prepass: convert K,V to fp16 in MMA-friendly layouts ----
extern "C" __global__ void __launch_bounds__(256)
kv_half(const float* __restrict__ ks, const float* __restrict__ vs)
{
    const int i = blockIdx.x * 256 + threadIdx.x;   // 524288 threads

    // K: thread converts 8 dims of one key row -> uint4 (8 halves)
    {
        const int h = i >> 15;                      // 32768 chunks/head
        const int rem = i & 32767;
        const int n = rem >> 3, c = rem & 7;        // key, chunk of 8 dims
        const float* src = ks + ((size_t)h * KLEN + n) * DIM + c * 8;
        float4 v0 = *(const float4*)(src);
        float4 v1 = *(const float4*)(src + 4);
        uint4 r;
        r.x = packh2(v0.x, v0.y); r.y = packh2(v0.z, v0.w);
        r.z = packh2(v1.x, v1.y); r.w = packh2(v1.z, v1.w);
        *(uint4*)(g_Kh + ((size_t)h * KLEN + n) * 32 + c * 4) = r;
    }
    // V: thread makes 4 half2 words {V[2kp][n],V[2kp+1][n]} for n..n+3
    {
        const int h = i >> 15;
        const int rem = i & 32767;
        const int kp = rem >> 4, c = rem & 15;
        const int n0 = c * 4;
        const float* srcA = vs + ((size_t)h * KLEN + 2 * kp) * DIM + n0;
        const float* srcB = srcA + DIM;
        float4 a = *(const float4*)srcA;
        float4 bb = *(const float4*)srcB;
        uint4 r;
        r.x = packh2(a.x, bb.x); r.y = packh2(a.y, bb.y);
        r.z = packh2(a.z, bb.z); r.w = packh2(a.w, bb.w);
        *(uint4*)(g_Vh + ((size_t)h * (KLEN / 2) + kp) * 64 + n0) = r;
    }
}

extern "C" __global__ void __launch_bounds__(NTHREADS, 2)
fa_hmma_reg(const float* __restrict__ qs, const unsigned int* __restrict__ maskw,
            float* __restrict__ out)
{
    extern __shared__ uint32_t smw[];
    const uint32_t sb = smem_u32(smw);

    const int tid  = threadIdx.x;
    const int w    = tid >> 5;
    const int lane = tid & 31;
    const int g    = lane >> 2;   // row within 8
    const int b    = lane & 3;    // k/col selector

    const int head = blockIdx.y;
    const int q0   = blockIdx.x * BQ;
    const int r0   = w * 32 + g;             // q rows r0, +8, +16, +24

    const float qscale = 0.125f * 1.44269504088896340736f;  // 1/sqrt(D)*log2(e)
    const float* qg = qs + ((size_t)head * QLEN + q0) * DIM;
    const uint32_t* kg = g_Kh + (size_t)head * KLEN * 32;
    const uint32_t* vg = g_Vh + (size_t)head * (KLEN / 2) * 64;

    // ---- prologue: prefetch stage 0 (K rows 128B, V kp-rows 256B) ----
    {
        #pragma unroll
        for (int i = 0; i < 4; i++) {
            const int idx = tid + NTHREADS * i;
            const int kr = idx >> 3, kp8 = (idx & 7) * 4;         // K: row, word chunk
            cp16(sb + (kr * KSW + kp8) * 4, kg + (size_t)kr * 32 + kp8);
            const int vr = idx >> 4, vp = (idx & 15) * 4;         // V: kp-row, word chunk
            cp16(sb + (STAGE_K_WORDS + vr * VSW + vp) * 4, vg + (size_t)vr * 64 + vp);
        }
        CP_COMMIT();
    }

    // ---- persistent Q A-fragments (fp16 pairs; 4 ktiles x 8 regs) ----
    uint32_t qa[4][8];
    {
        const float* q0p = qg + (size_t)r0 * DIM;
        const float* q1p = q0p + 8 * DIM;
        const float* q2p = q0p + 16 * DIM;
        const float* q3p = q0p + 24 * DIM;
        #pragma unroll
        for (int kc = 0; kc < 4; kc++) {
            const int kA = kc * 16 + 2 * b;        // pair cols kA,kA+1
            const int kB = kA + 8;                 // pair cols kB,kB+1
            qa[kc][0] = packh2(q0p[kA] * qscale, q0p[kA + 1] * qscale);
            qa[kc][1] = packh2(q1p[kA] * qscale, q1p[kA + 1] * qscale);
            qa[kc][2] = packh2(q0p[kB] * qscale, q0p[kB + 1] * qscale);
            qa[kc][3] = packh2(q1p[kB] * qscale, q1p[kB + 1] * qscale);
            qa[kc][4] = packh2(q2p[kA] * qscale, q2p[kA + 1] * qscale);
            qa[kc][5] = packh2(q3p[kA] * qscale, q3p[kA + 1] * qscale);
            qa[kc][6] = packh2(q2p[kB] * qscale, q2p[kB + 1] * qscale);
            qa[kc][7] = packh2(q3p[kB] * qscale, q3p[kB + 1] * qscale);
        }
    }

    float o[8][8];
    #pragma unroll
    for (int j = 0; j < 8; j++)
        #pragma unroll
        for (int e = 0; e < 8; e++) o[j][e] = 0.0f;
    float mrun[4] = {-1e30f, -1e30f, -1e30f, -1e30f};
    float lrun[4] = {0.0f, 0.0f, 0.0f, 0.0f};

    for (int it = 0; it < NITER; it++) {
        const int k0 = it * BK;
        const int stage = it & 1;
        const int kb = k0 >> 2;

        // ---- prefetch next tile into other stage ----
        {
            const int knx = (it + 1 < NITER ? it + 1 : it) * BK;
            const uint32_t sbase = sb + ((1 - stage) * STAGE_WORDS) * 4;
            const uint32_t* kgn = kg + (size_t)knx * 32;
            const uint32_t* vgn = vg + (size_t)(knx >> 1) * 64;
            #pragma unroll
            for (int i = 0; i < 4; i++) {
                const int idx = tid + NTHREADS * i;
                const int kr = idx >> 3, kp8 = (idx & 7) * 4;
                cp16(sbase + (kr * KSW + kp8) * 4, kgn + (size_t)kr * 32 + kp8);
                const int vr = idx >> 4, vp = (idx & 15) * 4;
                cp16(sbase + (STAGE_K_WORDS + vr * VSW + vp) * 4, vgn + (size_t)vr * 64 + vp);
            }
            CP_COMMIT();
        }
        CP_WAIT1();          // this stage's data landed
        __syncthreads();     // all threads' data visible; prev-iter reads done

        const uint32_t* KsU = smw + stage * STAGE_WORDS;
        const uint32_t* VsU = KsU + STAGE_K_WORDS;

        // ---- S = Q @ K^T : fp16 m16n8k16, B frag shared by both row-blocks ----
        float sacc[8][8];
        #pragma unroll
        for (int j = 0; j < 8; j++)
            #pragma unroll
            for (int e = 0; e < 8; e++) sacc[j][e] = 0.0f;

        #pragma unroll
        for (int kc = 0; kc < 4; kc++) {
            #pragma unroll
            for (int j = 0; j < 8; j++) {
                const uint32_t* kp = &KsU[(j * 8 + g) * KSW + kc * 8 + b];
                const uint32_t kb0 = kp[0], kb1 = kp[4];
                mma_f16(&sacc[j][0], &qa[kc][0], kb0, kb1);
                mma_f16(&sacc[j][4], &qa[kc][4], kb0, kb1);
            }
        }

        // ---- mask (robust word-of-4; all-true -> never taken) ----
        #pragma unroll
        for (int j = 0; j < 8; j++) {
            if (maskw[kb + 2 * j + (b >> 1)] == 0u) {
                #pragma unroll
                for (int e = 0; e < 8; e++) sacc[j][e] = -1e30f;
            }
        }

        // ---- online softmax (log2 domain), 4 row-blocks ----
        float m[4] = {-1e30f, -1e30f, -1e30f, -1e30f};
        #pragma unroll
        for (int j = 0; j < 8; j++)
            #pragma unroll
            for (int i = 0; i < 4; i++)
                m[i] = fmaxf(m[i], fmaxf(sacc[j][2 * i], sacc[j][2 * i + 1]));
        #pragma unroll
        for (int i = 0; i < 4; i++) {
            m[i] = fmaxf(m[i], __shfl_xor_sync(0xffffffffu, m[i], 1));
            m[i] = fmaxf(m[i], __shfl_xor_sync(0xffffffffu, m[i], 2));
        }
        float al[4];
        #pragma unroll
        for (int i = 0; i < 4; i++) {
            const float mn = fmaxf(mrun[i], m[i]);
            al[i] = fast_exp2(mrun[i] - mn);   // f32 ex2 for the rescale factor
            mrun[i] = mn;
        }

        // packed f16x2 exp; half2 {p(2b), p(2b+1)} IS the PV A-fragment word
        uint32_t ph[8][4];
        #pragma unroll
        for (int j = 0; j < 8; j++) {
            #pragma unroll
            for (int i = 0; i < 4; i++) {
                __half2 h = h2exp2(__floats2half2_rn(
                    sacc[j][2 * i] - mrun[i], sacc[j][2 * i + 1] - mrun[i]));
                ph[j][i] = *reinterpret_cast<uint32_t*>(&h);
            }
        }

        // ---- rescale O ----
        #pragma unroll
        for (int j = 0; j < 8; j++)
            #pragma unroll
            for (int i = 0; i < 4; i++) {
                o[j][2 * i]     *= al[i];
                o[j][2 * i + 1] *= al[i];
            }

        // ---- O += P @ V : A-fragments directly from ph registers.
        //      Row sums l via a ones-column MMA (no shuffles, no adds). ----
        float lacc0[4] = {0.f, 0.f, 0.f, 0.f};
        float lacc1[4] = {0.f, 0.f, 0.f, 0.f};
        #pragma unroll
        for (int kc = 0; kc < 4; kc++) {
            uint32_t pa0[4] = {ph[2*kc][0], ph[2*kc][1], ph[2*kc+1][0], ph[2*kc+1][1]};
            uint32_t pa1[4] = {ph[2*kc][2], ph[2*kc][3], ph[2*kc+1][2], ph[2*kc+1][3]};
            #pragma unroll
            for (int j = 0; j < 8; j++) {
                const uint32_t v0 = VsU[(kc * 8 + b)     * VSW + j * 8 + g];
                const uint32_t v1 = VsU[(kc * 8 + b + 4) * VSW + j * 8 + g];
                mma_f16(&o[j][0], pa0, v0, v1);
                mma_f16(&o[j][4], pa1, v0, v1);
            }
            mma_f16(lacc0, pa0, ONESH2, ONESH2);
            mma_f16(lacc1, pa1, ONESH2, ONESH2);
        }
        // lacc d-layout: d0=(row g), d2=(row g+8) — row sums replicated per col
        lrun[0] = lrun[0] * al[0] + lacc0[0];
        lrun[1] = lrun[1] * al[1] + lacc0[2];
        lrun[2] = lrun[2] * al[2] + lacc1[0];
        lrun[3] = lrun[3] * al[3] + lacc1[2];

        __syncthreads();  // everyone done reading this stage before it is re-filled
    }

    // ---- epilogue: normalize + store ----
    {
        float inv[4];
        #pragma unroll
        for (int i = 0; i < 4; i++) inv[i] = (lrun[i] > 0.0f) ? (1.0f / lrun[i]) : 0.0f;
        float* orow = out + ((size_t)head * QLEN + q0 + r0) * DIM;
        #pragma unroll
        for (int j = 0; j < 8; j++) {
            const int col = j * 8 + 2 * b;
            *(float2*)&orow[ 0 * DIM + col] = make_float2(o[j][0] * inv[0], o[j][1] * inv[0]);
            *(float2*)&orow[ 8 * DIM + col] = make_float2(o[j][2] * inv[1], o[j][3] * inv[1]);
            *(float2*)&orow[16 * DIM + col] = make_float2(o[j][4] * inv[2], o[j][5] * inv[2]);
            *(float2*)&orow[24 * DIM + col] = make_float2(o[j][6] * inv[3], o[j][7] * inv[3]);
        }
    }
}

extern "C" void kernel_launch(void* const* d_in, const int* in_sizes, int n_in,
                              void* d_out, int out_size)
{
    const float* qs = (const float*)d_in[0];
    const float* ks = (const float*)d_in[1];
    const float* vs = (const float*)d_in[2];
    const unsigned int* maskw = (const unsigned int*)d_in[3];
    float* out = (float*)d_out;

    // prepass: fp16-convert K,V into MMA-pair layouts
    kv_half<<<2048, 256>>>(ks, vs);

    cudaFuncSetAttribute(fa_hmma_reg, cudaFuncAttributeMaxDynamicSharedMemorySize, SMEM_BYTES);
    dim3 grid(QLEN / BQ, NHEAD);
    fa_hmma_reg<<<grid, NTHREADS, SMEM_BYTES>>>(qs, maskw, out);
}